// round 10
// baseline (speedup 1.0000x reference)
#include <cuda_runtime.h>
#include <cuda_bf16.h>
#include <mma.h>
#include <math.h>
#include <stdint.h>

using namespace nvcuda;

// ---------------------------------------------------------------------------
// Problem constants: B=4, S=2048, E=2048, H=16, D=128
// ---------------------------------------------------------------------------
#define BB   4
#define SS   2048
#define EE   2048
#define HH   16
#define DD   128
#define MM   (BB * SS)        // 8192 rows
#define QKVN (3 * EE)         // 6144

// ---------------------------------------------------------------------------
// Scratch (device globals -- allocation-free rule). 268 MB total.
// ---------------------------------------------------------------------------
__device__ float g_q[(size_t)BB * HH * SS * DD];    // 67 MB, [B,H,S,D]
__device__ float g_k[(size_t)BB * HH * SS * DD];
__device__ float g_v[(size_t)BB * HH * SS * DD];
__device__ float g_y[(size_t)MM * EE];              // 67 MB, [B,S,E]

// ---------------------------------------------------------------------------
// Software tf32 rounding (round-to-nearest to 10 mantissa bits) -- pure
// integer ops, no inline asm.
// ---------------------------------------------------------------------------
__device__ __forceinline__ float f2tf32f(float x) {
    uint32_t u = __float_as_uint(x);
    u += 0x1000u;
    u &= 0xFFFFE000u;
    return __uint_as_float(u);
}

// ---------------------------------------------------------------------------
// tf32 tensor-core GEMM via nvcuda::wmma (m16n16k8) -- unchanged from R9.
// ---------------------------------------------------------------------------
#define KSTEP 16
#define SSTR  136

template <int SPLIT_QKV>
__global__ __launch_bounds__(256, 2)
void gemm_tf32(const float* __restrict__ A, const float* __restrict__ B,
               float* __restrict__ C0, float* __restrict__ C1,
               float* __restrict__ C2, int M, int N, int K)
{
    __shared__ float As[2][KSTEP][SSTR];   // [k][m]  (A transposed -> col_major A)
    __shared__ float Bs[2][KSTEP][SSTR];   // [k][n]  (row_major B)

    const int tid  = threadIdx.x;
    const int wid  = tid >> 5;
    const int wm   = wid & 1;
    const int wn   = wid >> 1;
    const int bm0  = blockIdx.y * 128;
    const int bn0  = blockIdx.x * 128;

    const int a_row = tid >> 2;
    const int a_kc4 = (tid & 3) * 4;
    const int b_k  = tid >> 5;
    const int b_n4 = (tid & 31) * 4;

    const float* Ag = A + (size_t)(bm0 + a_row) * K + a_kc4;
    const float* Bg = B + (size_t)b_k * N + bn0 + b_n4;

    {
        #pragma unroll
        for (int i = 0; i < 2; i++) {
            float4 av = *(const float4*)(Ag + (size_t)(i * 64) * K);
            const int r = a_row + i * 64;
            As[0][a_kc4 + 0][r] = f2tf32f(av.x);
            As[0][a_kc4 + 1][r] = f2tf32f(av.y);
            As[0][a_kc4 + 2][r] = f2tf32f(av.z);
            As[0][a_kc4 + 3][r] = f2tf32f(av.w);
            float4 bv = *(const float4*)(Bg + (size_t)(i * 8) * N);
            bv.x = f2tf32f(bv.x); bv.y = f2tf32f(bv.y);
            bv.z = f2tf32f(bv.z); bv.w = f2tf32f(bv.w);
            *(float4*)&Bs[0][b_k + i * 8][b_n4] = bv;
        }
    }
    __syncthreads();

    wmma::fragment<wmma::accumulator, 16, 16, 8, float> acc[4][2];
    #pragma unroll
    for (int mi = 0; mi < 4; mi++)
        #pragma unroll
        for (int ni = 0; ni < 2; ni++)
            wmma::fill_fragment(acc[mi][ni], 0.0f);

    const int m0 = wm * 64;
    const int n0 = wn * 32;
    const int niters = K >> 4;

    float4 pa[2], pb[2];
    for (int t = 0; t < niters; t++) {
        const int buf = t & 1;
        if (t + 1 < niters) {
            const int kt = (t + 1) * KSTEP;
            #pragma unroll
            for (int i = 0; i < 2; i++) {
                pa[i] = *(const float4*)(Ag + (size_t)(i * 64) * K + kt);
                pb[i] = *(const float4*)(Bg + (size_t)(kt + i * 8) * N);
            }
        }

        #pragma unroll
        for (int sub = 0; sub < 2; sub++) {
            const int kk = sub * 8;
            wmma::fragment<wmma::matrix_a, 16, 16, 8,
                           wmma::precision::tf32, wmma::col_major> afrag[4];
            wmma::fragment<wmma::matrix_b, 16, 16, 8,
                           wmma::precision::tf32, wmma::row_major> bfrag[2];
            #pragma unroll
            for (int mi = 0; mi < 4; mi++)
                wmma::load_matrix_sync(afrag[mi], &As[buf][kk][m0 + mi * 16], SSTR);
            #pragma unroll
            for (int ni = 0; ni < 2; ni++)
                wmma::load_matrix_sync(bfrag[ni], &Bs[buf][kk][n0 + ni * 16], SSTR);
            #pragma unroll
            for (int mi = 0; mi < 4; mi++)
                #pragma unroll
                for (int ni = 0; ni < 2; ni++)
                    wmma::mma_sync(acc[mi][ni], afrag[mi], bfrag[ni], acc[mi][ni]);
        }

        if (t + 1 < niters) {
            const int nb = buf ^ 1;
            #pragma unroll
            for (int i = 0; i < 2; i++) {
                const int r = a_row + i * 64;
                As[nb][a_kc4 + 0][r] = f2tf32f(pa[i].x);
                As[nb][a_kc4 + 1][r] = f2tf32f(pa[i].y);
                As[nb][a_kc4 + 2][r] = f2tf32f(pa[i].z);
                As[nb][a_kc4 + 3][r] = f2tf32f(pa[i].w);
                float4 bv = pb[i];
                bv.x = f2tf32f(bv.x); bv.y = f2tf32f(bv.y);
                bv.z = f2tf32f(bv.z); bv.w = f2tf32f(bv.w);
                *(float4*)&Bs[nb][b_k + i * 8][b_n4] = bv;
            }
        }
        __syncthreads();
    }

    if (SPLIT_QKV) {
        const int which = bn0 >> 11;
        const int h     = (bn0 & 2047) >> 7;
        const int b     = bm0 >> 11;
        const int s0    = bm0 & 2047;
        float* dstb = (which == 0 ? C0 : (which == 1 ? C1 : C2))
                      + ((size_t)(b * HH + h) * SS) * DD;
        #pragma unroll
        for (int mi = 0; mi < 4; mi++)
            #pragma unroll
            for (int ni = 0; ni < 2; ni++)
                wmma::store_matrix_sync(dstb + (size_t)(s0 + m0 + mi * 16) * DD + n0 + ni * 16,
                                        acc[mi][ni], DD, wmma::mem_row_major);
    } else {
        #pragma unroll
        for (int mi = 0; mi < 4; mi++)
            #pragma unroll
            for (int ni = 0; ni < 2; ni++)
                wmma::store_matrix_sync(C0 + (size_t)(bm0 + m0 + mi * 16) * N + bn0 + n0 + ni * 16,
                                        acc[mi][ni], N, wmma::mem_row_major);
    }
}

// ---------------------------------------------------------------------------
// RoPE + QK-RMSNorm, in-place on q,k in [B,H,S,D] layout (unchanged).
// ---------------------------------------------------------------------------
__global__ __launch_bounds__(64)
void rope_norm(float* __restrict__ q, float* __restrict__ k)
{
    const int h = blockIdx.x;
    const int s = blockIdx.y;
    const int b = blockIdx.z;
    const int j = threadIdx.x;

    const size_t base = ((size_t)((b * HH + h) * SS + s)) * DD + 2 * j;
    const float2 qp = *(const float2*)(q + base);
    const float2 kp = *(const float2*)(k + base);

    const float ex   = (float)(2 * j) * (1.0f / (float)DD);
    const float invf = 1.0f / powf(10000.0f, ex);
    const float fr   = (float)s * invf;
    float sn, cs;
    sincosf(fr, &sn, &cs);

    const float q0 = qp.x * cs - qp.y * sn;
    const float q1 = qp.x * sn + qp.y * cs;
    const float k0 = kp.x * cs - kp.y * sn;
    const float k1 = kp.x * sn + kp.y * cs;

    float sq = q0 * q0 + q1 * q1;
    float sk = k0 * k0 + k1 * k1;
    #pragma unroll
    for (int off = 16; off; off >>= 1) {
        sq += __shfl_xor_sync(0xffffffffu, sq, off);
        sk += __shfl_xor_sync(0xffffffffu, sk, off);
    }
    __shared__ float sh[4];
    if ((j & 31) == 0) { sh[(j >> 5) * 2] = sq; sh[(j >> 5) * 2 + 1] = sk; }
    __syncthreads();
    const float tq = sh[0] + sh[2];
    const float tk = sh[1] + sh[3];
    const float rq = rsqrtf(tq * (1.0f / (float)DD) + 1e-5f);
    const float rk = rsqrtf(tk * (1.0f / (float)DD) + 1e-5f);

    *(float2*)(q + base) = make_float2(q0 * rq, q1 * rq);
    *(float2*)(k + base) = make_float2(k0 * rk, k1 * rk);
}

// ---------------------------------------------------------------------------
// Tensor-core causal flash attention (wmma tf32).
// Key fact: qk-rmsnorm bounds |score| <= sqrt(128) ~= 11.33, so exp() cannot
// overflow -> NO online max, NO O-rescaling. O stays in wmma accumulator
// fragments across the whole KV loop (no layout assumptions anywhere).
// QK^T uses split-tf32 (hi+lo, 3 mmas) -> fp32-grade scores (softmax-amplified
// path). PV uses single tf32 (linear averaging path).
// Grid: (S/64, B*H), 256 threads = 8 warps (2m x 4n).
// ---------------------------------------------------------------------------
#define QKLD 136    // padded row stride for 128-wide tiles
#define PLD  72     // padded row stride for 64-wide P tile
#define FL2_FLOATS (5 * 64 * QKLD + 64 * PLD + 64)
#define FL2_BYTES  (FL2_FLOATS * 4)

__global__ __launch_bounds__(256)
void flash_attn_tc(const float* __restrict__ Qg, const float* __restrict__ Kg,
                   const float* __restrict__ Vg, float* __restrict__ Yg)
{
    const int bh  = blockIdx.y;
    const int qt  = blockIdx.x;
    const int qm0 = qt * 64;
    const int b   = bh >> 4;
    const int h   = bh & 15;

    extern __shared__ float sm[];
    float* QH = sm;                  // [64][136] q hi (tf32)
    float* QL = QH + 64 * QKLD;      // [64][136] q lo (tf32 residual)
    float* KH = QL + 64 * QKLD;      // [64][136] k hi   (reused for O at end)
    float* KL = KH + 64 * QKLD;      // [64][136] k lo
    float* VS = KL + 64 * QKLD;      // [64][136] v (tf32)
    float* PS = VS + 64 * QKLD;      // [64][72]  scores / P
    float* LS = PS + 64 * PLD;       // [64]      running row sums of p

    const int tid = threadIdx.x;
    const int wid = tid >> 5;
    const int wm  = wid & 1;         // m half (0..1)
    const int wn  = wid >> 1;        // n quarter (0..3)
    const int m0  = wm * 32;

    const float* Qb = Qg + (size_t)bh * SS * DD;
    const float* Kb = Kg + (size_t)bh * SS * DD;
    const float* Vb = Vg + (size_t)bh * SS * DD;

    // Load Q tile, split into tf32 hi + lo
    for (int e = tid; e < 64 * 32; e += 256) {
        const int i  = e >> 5;
        const int d4 = (e & 31) << 2;
        float4 v = *(const float4*)(Qb + (size_t)(qm0 + i) * DD + d4);
        float h0 = f2tf32f(v.x), h1 = f2tf32f(v.y);
        float h2 = f2tf32f(v.z), h3 = f2tf32f(v.w);
        QH[i * QKLD + d4 + 0] = h0;  QL[i * QKLD + d4 + 0] = f2tf32f(v.x - h0);
        QH[i * QKLD + d4 + 1] = h1;  QL[i * QKLD + d4 + 1] = f2tf32f(v.y - h1);
        QH[i * QKLD + d4 + 2] = h2;  QL[i * QKLD + d4 + 2] = f2tf32f(v.z - h2);
        QH[i * QKLD + d4 + 3] = h3;  QL[i * QKLD + d4 + 3] = f2tf32f(v.w - h3);
    }
    if (tid < 64) LS[tid] = 0.0f;

    // Persistent O accumulators: warp tile 32(m) x 32(n) of the 64x128 O
    wmma::fragment<wmma::accumulator, 16, 16, 8, float> ofrag[2][2];
    #pragma unroll
    for (int mi = 0; mi < 2; mi++)
        #pragma unroll
        for (int ni = 0; ni < 2; ni++)
            wmma::fill_fragment(ofrag[mi][ni], 0.0f);

    const float scale = 0.08838834764831845f;   // 1/sqrt(128)

    for (int kt = 0; kt <= qt; kt++) {
        const int kn0 = kt * 64;
        __syncthreads();   // previous iter's P/V reads done (covers Q/LS on kt=0)

        // Load K (split hi/lo) and V (tf32) tiles
        for (int e = tid; e < 64 * 32; e += 256) {
            const int j  = e >> 5;
            const int d4 = (e & 31) << 2;
            float4 kv = *(const float4*)(Kb + (size_t)(kn0 + j) * DD + d4);
            float h0 = f2tf32f(kv.x), h1 = f2tf32f(kv.y);
            float h2 = f2tf32f(kv.z), h3 = f2tf32f(kv.w);
            KH[j * QKLD + d4 + 0] = h0;  KL[j * QKLD + d4 + 0] = f2tf32f(kv.x - h0);
            KH[j * QKLD + d4 + 1] = h1;  KL[j * QKLD + d4 + 1] = f2tf32f(kv.y - h1);
            KH[j * QKLD + d4 + 2] = h2;  KL[j * QKLD + d4 + 2] = f2tf32f(kv.z - h2);
            KH[j * QKLD + d4 + 3] = h3;  KL[j * QKLD + d4 + 3] = f2tf32f(kv.w - h3);
            float4 vv = *(const float4*)(Vb + (size_t)(kn0 + j) * DD + d4);
            VS[j * QKLD + d4 + 0] = f2tf32f(vv.x);
            VS[j * QKLD + d4 + 1] = f2tf32f(vv.y);
            VS[j * QKLD + d4 + 2] = f2tf32f(vv.z);
            VS[j * QKLD + d4 + 3] = f2tf32f(vv.w);
        }
        __syncthreads();

        // --- S = Q K^T (split-tf32: hi*hi + lo*hi + hi*lo) ---
        // Warp score tile: 32(m) x 16(n); n strip = wn*16
        {
            const int n0 = wn * 16;
            wmma::fragment<wmma::accumulator, 16, 16, 8, float> sf[2];
            #pragma unroll
            for (int mi = 0; mi < 2; mi++) wmma::fill_fragment(sf[mi], 0.0f);

            #pragma unroll 4
            for (int k0 = 0; k0 < DD; k0 += 8) {
                wmma::fragment<wmma::matrix_a, 16, 16, 8,
                               wmma::precision::tf32, wmma::row_major> ah[2], al[2];
                wmma::fragment<wmma::matrix_b, 16, 16, 8,
                               wmma::precision::tf32, wmma::col_major> bh_, bl_;
                #pragma unroll
                for (int mi = 0; mi < 2; mi++) {
                    wmma::load_matrix_sync(ah[mi], &QH[(m0 + mi * 16) * QKLD + k0], QKLD);
                    wmma::load_matrix_sync(al[mi], &QL[(m0 + mi * 16) * QKLD + k0], QKLD);
                }
                wmma::load_matrix_sync(bh_, &KH[n0 * QKLD + k0], QKLD);
                wmma::load_matrix_sync(bl_, &KL[n0 * QKLD + k0], QKLD);
                #pragma unroll
                for (int mi = 0; mi < 2; mi++) {
                    wmma::mma_sync(sf[mi], ah[mi], bh_, sf[mi]);
                    wmma::mma_sync(sf[mi], al[mi], bh_, sf[mi]);
                    wmma::mma_sync(sf[mi], ah[mi], bl_, sf[mi]);
                }
            }
            #pragma unroll
            for (int mi = 0; mi < 2; mi++) {
                #pragma unroll
                for (int t = 0; t < sf[mi].num_elements; t++) sf[mi].x[t] *= scale;
                wmma::store_matrix_sync(&PS[(m0 + mi * 16) * PLD + n0], sf[mi],
                                        PLD, wmma::mem_row_major);
            }
        }
        __syncthreads();

        // --- softmax (no max shift: |s| <= 11.33): p = exp(s), mask, round ---
        {
            const int r    = tid >> 2;
            const int c0   = (tid & 3) * 16;
            const int rowg = qm0 + r;
            const bool diag = (kt == qt);
            float rs = 0.0f;
            #pragma unroll
            for (int c = 0; c < 16; c++) {
                const int col = c0 + c;
                float s = PS[r * PLD + col];
                float p = (diag && (kn0 + col) > rowg) ? 0.0f : __expf(s);
                p = f2tf32f(p);
                PS[r * PLD + col] = p;
                rs += p;
            }
            rs += __shfl_xor_sync(0xffffffffu, rs, 1);
            rs += __shfl_xor_sync(0xffffffffu, rs, 2);
            if ((tid & 3) == 0) LS[r] += rs;
        }
        __syncthreads();

        // --- O += P V (single tf32) ---
        {
            const int n0p = wn * 32;
            #pragma unroll
            for (int k0 = 0; k0 < 64; k0 += 8) {
                wmma::fragment<wmma::matrix_a, 16, 16, 8,
                               wmma::precision::tf32, wmma::row_major> ap[2];
                wmma::fragment<wmma::matrix_b, 16, 16, 8,
                               wmma::precision::tf32, wmma::row_major> bv[2];
                #pragma unroll
                for (int mi = 0; mi < 2; mi++)
                    wmma::load_matrix_sync(ap[mi], &PS[(m0 + mi * 16) * PLD + k0], PLD);
                #pragma unroll
                for (int ni = 0; ni < 2; ni++)
                    wmma::load_matrix_sync(bv[ni], &VS[k0 * QKLD + n0p + ni * 16], QKLD);
                #pragma unroll
                for (int mi = 0; mi < 2; mi++)
                    #pragma unroll
                    for (int ni = 0; ni < 2; ni++)
                        wmma::mma_sync(ofrag[mi][ni], ap[mi], bv[ni], ofrag[mi][ni]);
            }
        }
    }

    // --- epilogue: O -> smem (reuse KH), normalize by LS, write y [B,S,E] ---
    __syncthreads();
    {
        const int n0p = wn * 32;
        #pragma unroll
        for (int mi = 0; mi < 2; mi++)
            #pragma unroll
            for (int ni = 0; ni < 2; ni++)
                wmma::store_matrix_sync(&KH[(m0 + mi * 16) * QKLD + n0p + ni * 16],
                                        ofrag[mi][ni], QKLD, wmma::mem_row_major);
    }
    __syncthreads();
    for (int e = tid; e < 64 * 32; e += 256) {
        const int i  = e >> 5;
        const int d4 = (e & 31) << 2;
        const float invl = 1.0f / LS[i];
        float* yp = Yg + ((size_t)(b * SS + qm0 + i)) * EE + h * DD + d4;
        *(float4*)yp = make_float4(KH[i * QKLD + d4 + 0] * invl,
                                   KH[i * QKLD + d4 + 1] * invl,
                                   KH[i * QKLD + d4 + 2] * invl,
                                   KH[i * QKLD + d4 + 3] * invl);
    }
}

// ---------------------------------------------------------------------------
// Launch
// ---------------------------------------------------------------------------
extern "C" void kernel_launch(void* const* d_in, const int* in_sizes, int n_in,
                              void* d_out, int out_size)
{
    const float* x      = (const float*)d_in[0];
    const float* w_qkv  = (const float*)d_in[1];
    const float* w_proj = (const float*)d_in[2];
    float* out          = (float*)d_out;

    float *q_p, *k_p, *v_p, *y_p;
    cudaGetSymbolAddress((void**)&q_p, g_q);
    cudaGetSymbolAddress((void**)&k_p, g_k);
    cudaGetSymbolAddress((void**)&v_p, g_v);
    cudaGetSymbolAddress((void**)&y_p, g_y);

    cudaFuncSetAttribute(flash_attn_tc, cudaFuncAttributeMaxDynamicSharedMemorySize,
                         FL2_BYTES);

    // 1) QKV projection (tf32 wmma) with fused head-split
    gemm_tf32<1><<<dim3(QKVN / 128, MM / 128), 256>>>(x, w_qkv, q_p, k_p, v_p,
                                                      MM, QKVN, EE);

    // 2) RoPE + RMSNorm in-place on q,k
    rope_norm<<<dim3(HH, SS, BB), 64>>>(q_p, k_p);

    // 3) Tensor-core causal flash attention
    flash_attn_tc<<<dim3(SS / 64, BB * HH), 256, FL2_BYTES>>>(q_p, k_p, v_p, y_p);

    // 4) Output projection (tf32 wmma)
    gemm_tf32<0><<<dim3(EE / 128, MM / 128), 256>>>(y_p, w_proj, out, nullptr, nullptr,
                                                    MM, EE, EE);
}

// round 13
// speedup vs baseline: 1.2632x; 1.2632x over previous
#include <cuda_runtime.h>
#include <cuda_bf16.h>
#include <mma.h>
#include <math.h>
#include <stdint.h>

using namespace nvcuda;

// ---------------------------------------------------------------------------
// Problem constants: B=4, S=2048, E=2048, H=16, D=128
// ---------------------------------------------------------------------------
#define BB   4
#define SS   2048
#define EE   2048
#define HH   16
#define DD   128
#define MM   (BB * SS)
#define QKVN (3 * EE)

__device__ float g_q[(size_t)BB * HH * SS * DD];
__device__ float g_k[(size_t)BB * HH * SS * DD];
__device__ float g_v[(size_t)BB * HH * SS * DD];
__device__ float g_y[(size_t)MM * EE];

// Software tf32 rounding (RN to 10 mantissa bits), pure integer ops.
__device__ __forceinline__ float f2tf32f(float x) {
    uint32_t u = __float_as_uint(x);
    u += 0x1000u;
    u &= 0xFFFFE000u;
    return __uint_as_float(u);
}

// ---------------------------------------------------------------------------
// tf32 wmma GEMM (m16n16k8) -- unchanged from R9 (passed, 46% tensor pipe).
// ---------------------------------------------------------------------------
#define KSTEP 16
#define SSTR  136

template <int SPLIT_QKV>
__global__ __launch_bounds__(256, 2)
void gemm_tf32(const float* __restrict__ A, const float* __restrict__ B,
               float* __restrict__ C0, float* __restrict__ C1,
               float* __restrict__ C2, int M, int N, int K)
{
    __shared__ float As[2][KSTEP][SSTR];
    __shared__ float Bs[2][KSTEP][SSTR];

    const int tid  = threadIdx.x;
    const int wid  = tid >> 5;
    const int wm   = wid & 1;
    const int wn   = wid >> 1;
    const int bm0  = blockIdx.y * 128;
    const int bn0  = blockIdx.x * 128;

    const int a_row = tid >> 2;
    const int a_kc4 = (tid & 3) * 4;
    const int b_k  = tid >> 5;
    const int b_n4 = (tid & 31) * 4;

    const float* Ag = A + (size_t)(bm0 + a_row) * K + a_kc4;
    const float* Bg = B + (size_t)b_k * N + bn0 + b_n4;

    {
        #pragma unroll
        for (int i = 0; i < 2; i++) {
            float4 av = *(const float4*)(Ag + (size_t)(i * 64) * K);
            const int r = a_row + i * 64;
            As[0][a_kc4 + 0][r] = f2tf32f(av.x);
            As[0][a_kc4 + 1][r] = f2tf32f(av.y);
            As[0][a_kc4 + 2][r] = f2tf32f(av.z);
            As[0][a_kc4 + 3][r] = f2tf32f(av.w);
            float4 bv = *(const float4*)(Bg + (size_t)(i * 8) * N);
            bv.x = f2tf32f(bv.x); bv.y = f2tf32f(bv.y);
            bv.z = f2tf32f(bv.z); bv.w = f2tf32f(bv.w);
            *(float4*)&Bs[0][b_k + i * 8][b_n4] = bv;
        }
    }
    __syncthreads();

    wmma::fragment<wmma::accumulator, 16, 16, 8, float> acc[4][2];
    #pragma unroll
    for (int mi = 0; mi < 4; mi++)
        #pragma unroll
        for (int ni = 0; ni < 2; ni++)
            wmma::fill_fragment(acc[mi][ni], 0.0f);

    const int m0 = wm * 64;
    const int n0 = wn * 32;
    const int niters = K >> 4;

    float4 pa[2], pb[2];
    for (int t = 0; t < niters; t++) {
        const int buf = t & 1;
        if (t + 1 < niters) {
            const int kt = (t + 1) * KSTEP;
            #pragma unroll
            for (int i = 0; i < 2; i++) {
                pa[i] = *(const float4*)(Ag + (size_t)(i * 64) * K + kt);
                pb[i] = *(const float4*)(Bg + (size_t)(kt + i * 8) * N);
            }
        }

        #pragma unroll
        for (int sub = 0; sub < 2; sub++) {
            const int kk = sub * 8;
            wmma::fragment<wmma::matrix_a, 16, 16, 8,
                           wmma::precision::tf32, wmma::col_major> afrag[4];
            wmma::fragment<wmma::matrix_b, 16, 16, 8,
                           wmma::precision::tf32, wmma::row_major> bfrag[2];
            #pragma unroll
            for (int mi = 0; mi < 4; mi++)
                wmma::load_matrix_sync(afrag[mi], &As[buf][kk][m0 + mi * 16], SSTR);
            #pragma unroll
            for (int ni = 0; ni < 2; ni++)
                wmma::load_matrix_sync(bfrag[ni], &Bs[buf][kk][n0 + ni * 16], SSTR);
            #pragma unroll
            for (int mi = 0; mi < 4; mi++)
                #pragma unroll
                for (int ni = 0; ni < 2; ni++)
                    wmma::mma_sync(acc[mi][ni], afrag[mi], bfrag[ni], acc[mi][ni]);
        }

        if (t + 1 < niters) {
            const int nb = buf ^ 1;
            #pragma unroll
            for (int i = 0; i < 2; i++) {
                const int r = a_row + i * 64;
                As[nb][a_kc4 + 0][r] = f2tf32f(pa[i].x);
                As[nb][a_kc4 + 1][r] = f2tf32f(pa[i].y);
                As[nb][a_kc4 + 2][r] = f2tf32f(pa[i].z);
                As[nb][a_kc4 + 3][r] = f2tf32f(pa[i].w);
                float4 bv = pb[i];
                bv.x = f2tf32f(bv.x); bv.y = f2tf32f(bv.y);
                bv.z = f2tf32f(bv.z); bv.w = f2tf32f(bv.w);
                *(float4*)&Bs[nb][b_k + i * 8][b_n4] = bv;
            }
        }
        __syncthreads();
    }

    if (SPLIT_QKV) {
        const int which = bn0 >> 11;
        const int h     = (bn0 & 2047) >> 7;
        const int b     = bm0 >> 11;
        const int s0    = bm0 & 2047;
        float* dstb = (which == 0 ? C0 : (which == 1 ? C1 : C2))
                      + ((size_t)(b * HH + h) * SS) * DD;
        #pragma unroll
        for (int mi = 0; mi < 4; mi++)
            #pragma unroll
            for (int ni = 0; ni < 2; ni++)
                wmma::store_matrix_sync(dstb + (size_t)(s0 + m0 + mi * 16) * DD + n0 + ni * 16,
                                        acc[mi][ni], DD, wmma::mem_row_major);
    } else {
        #pragma unroll
        for (int mi = 0; mi < 4; mi++)
            #pragma unroll
            for (int ni = 0; ni < 2; ni++)
                wmma::store_matrix_sync(C0 + (size_t)(bm0 + m0 + mi * 16) * N + bn0 + n0 + ni * 16,
                                        acc[mi][ni], N, wmma::mem_row_major);
    }
}

// ---------------------------------------------------------------------------
// RoPE + QK-RMSNorm, in-place (unchanged).
// ---------------------------------------------------------------------------
__global__ __launch_bounds__(64)
void rope_norm(float* __restrict__ q, float* __restrict__ k)
{
    const int h = blockIdx.x;
    const int s = blockIdx.y;
    const int b = blockIdx.z;
    const int j = threadIdx.x;

    const size_t base = ((size_t)((b * HH + h) * SS + s)) * DD + 2 * j;
    const float2 qp = *(const float2*)(q + base);
    const float2 kp = *(const float2*)(k + base);

    const float ex   = (float)(2 * j) * (1.0f / (float)DD);
    const float invf = 1.0f / powf(10000.0f, ex);
    const float fr   = (float)s * invf;
    float sn, cs;
    sincosf(fr, &sn, &cs);

    const float q0 = qp.x * cs - qp.y * sn;
    const float q1 = qp.x * sn + qp.y * cs;
    const float k0 = kp.x * cs - kp.y * sn;
    const float k1 = kp.x * sn + kp.y * cs;

    float sq = q0 * q0 + q1 * q1;
    float sk = k0 * k0 + k1 * k1;
    #pragma unroll
    for (int off = 16; off; off >>= 1) {
        sq += __shfl_xor_sync(0xffffffffu, sq, off);
        sk += __shfl_xor_sync(0xffffffffu, sk, off);
    }
    __shared__ float sh[4];
    if ((j & 31) == 0) { sh[(j >> 5) * 2] = sq; sh[(j >> 5) * 2 + 1] = sk; }
    __syncthreads();
    const float tq = sh[0] + sh[2];
    const float tk = sh[1] + sh[3];
    const float rq = rsqrtf(tq * (1.0f / (float)DD) + 1e-5f);
    const float rk = rsqrtf(tk * (1.0f / (float)DD) + 1e-5f);

    *(float2*)(q + base) = make_float2(q0 * rq, q1 * rq);
    *(float2*)(k + base) = make_float2(k0 * rk, k1 * rk);
}

// ---------------------------------------------------------------------------
// Tensor-core causal flash attention v2.
// 128 q-rows per CTA (2x amortization of K/V traffic + syncs), single-tf32
// QK and PV (rmsnorm bounds |s|<=11.33 -> no max shift, no O rescale; O
// persistent in wmma accumulators). Stride 132 (2-way instead of 4-way smem
// conflicts). Register prefetch of next K/V tile hides gmem latency.
// Grid: (S/128, B*H) = (16, 64). 256 threads = 8 warps (4m x 2n).
// ---------------------------------------------------------------------------
#define QKLD 132
#define PLD  68
#define FL3_FLOATS (128 * QKLD + 64 * QKLD + 64 * QKLD + 128 * PLD + 128)
#define FL3_BYTES  (FL3_FLOATS * 4)

__global__ __launch_bounds__(256, 1)
void flash_attn_tc(const float* __restrict__ Qg, const float* __restrict__ Kg,
                   const float* __restrict__ Vg, float* __restrict__ Yg)
{
    const int bh  = blockIdx.y;
    const int qt  = blockIdx.x;
    const int qm0 = qt * 128;
    const int b   = bh >> 4;
    const int h   = bh & 15;

    extern __shared__ float sm[];
    float* QS = sm;                  // [128][132] q (tf32), reused for O at end
    float* KS = QS + 128 * QKLD;     // [64][132]  k (tf32)
    float* VS = KS + 64 * QKLD;      // [64][132]  v (tf32)
    float* PS = VS + 64 * QKLD;      // [128][68]  scores / P
    float* LS = PS + 128 * PLD;      // [128]      running row sums

    const int tid = threadIdx.x;
    const int wid = tid >> 5;
    const int wm  = wid & 3;         // 0..3 (m)
    const int wn  = wid >> 2;        // 0..1 (n)
    const int m0  = wm * 32;

    const float* Qb = Qg + (size_t)bh * SS * DD;
    const float* Kb = Kg + (size_t)bh * SS * DD;
    const float* Vb = Vg + (size_t)bh * SS * DD;

    // Load Q tile (128x128), round to tf32
    for (int e = tid; e < 128 * 32; e += 256) {
        const int i  = e >> 5;
        const int d4 = (e & 31) << 2;
        float4 v = *(const float4*)(Qb + (size_t)(qm0 + i) * DD + d4);
        QS[i * QKLD + d4 + 0] = f2tf32f(v.x);
        QS[i * QKLD + d4 + 1] = f2tf32f(v.y);
        QS[i * QKLD + d4 + 2] = f2tf32f(v.z);
        QS[i * QKLD + d4 + 3] = f2tf32f(v.w);
    }
    if (tid < 128) LS[tid] = 0.0f;

    // Persistent O accumulators: warp tile 32(m) x 64(n) of 128x128 O
    wmma::fragment<wmma::accumulator, 16, 16, 8, float> ofrag[2][4];
    #pragma unroll
    for (int mi = 0; mi < 2; mi++)
        #pragma unroll
        for (int ni = 0; ni < 4; ni++)
            wmma::fill_fragment(ofrag[mi][ni], 0.0f);

    const float scale = 0.08838834764831845f;   // 1/sqrt(128)
    const int nkt = 2 * qt + 2;                 // kv tiles of 64 rows

    // loader geometry for K/V: 64x32 float4 = 2048 elems, 8 per thread
    // prefetch tile 0
    float4 kreg[8], vreg[8];
    #pragma unroll
    for (int i = 0; i < 8; i++) {
        const int e  = tid + i * 256;
        const int r  = e >> 5;
        const int d4 = (e & 31) << 2;
        kreg[i] = *(const float4*)(Kb + (size_t)r * DD + d4);
        vreg[i] = *(const float4*)(Vb + (size_t)r * DD + d4);
    }

    for (int kt = 0; kt < nkt; kt++) {
        const int kn0 = kt * 64;
        __syncthreads();   // prev iter done with KS/VS/PS (covers QS/LS on kt=0)

        // store prefetched K/V to smem (rounded)
        #pragma unroll
        for (int i = 0; i < 8; i++) {
            const int e  = tid + i * 256;
            const int r  = e >> 5;
            const int d4 = (e & 31) << 2;
            KS[r * QKLD + d4 + 0] = f2tf32f(kreg[i].x);
            KS[r * QKLD + d4 + 1] = f2tf32f(kreg[i].y);
            KS[r * QKLD + d4 + 2] = f2tf32f(kreg[i].z);
            KS[r * QKLD + d4 + 3] = f2tf32f(kreg[i].w);
            VS[r * QKLD + d4 + 0] = f2tf32f(vreg[i].x);
            VS[r * QKLD + d4 + 1] = f2tf32f(vreg[i].y);
            VS[r * QKLD + d4 + 2] = f2tf32f(vreg[i].z);
            VS[r * QKLD + d4 + 3] = f2tf32f(vreg[i].w);
        }
        __syncthreads();

        // prefetch next K/V tile (latency hidden behind QK+softmax+PV)
        if (kt + 1 < nkt) {
            const int kn1 = kn0 + 64;
            #pragma unroll
            for (int i = 0; i < 8; i++) {
                const int e  = tid + i * 256;
                const int r  = e >> 5;
                const int d4 = (e & 31) << 2;
                kreg[i] = *(const float4*)(Kb + (size_t)(kn1 + r) * DD + d4);
                vreg[i] = *(const float4*)(Vb + (size_t)(kn1 + r) * DD + d4);
            }
        }

        // --- S = Q K^T (single tf32), warp tile 32(m) x 32(n) ---
        {
            const int n0 = wn * 32;
            wmma::fragment<wmma::accumulator, 16, 16, 8, float> sf[2][2];
            #pragma unroll
            for (int mi = 0; mi < 2; mi++)
                #pragma unroll
                for (int ni = 0; ni < 2; ni++)
                    wmma::fill_fragment(sf[mi][ni], 0.0f);

            #pragma unroll 4
            for (int k0 = 0; k0 < DD; k0 += 8) {
                wmma::fragment<wmma::matrix_a, 16, 16, 8,
                               wmma::precision::tf32, wmma::row_major> aq[2];
                wmma::fragment<wmma::matrix_b, 16, 16, 8,
                               wmma::precision::tf32, wmma::col_major> bk[2];
                #pragma unroll
                for (int mi = 0; mi < 2; mi++)
                    wmma::load_matrix_sync(aq[mi], &QS[(m0 + mi * 16) * QKLD + k0], QKLD);
                #pragma unroll
                for (int ni = 0; ni < 2; ni++)
                    wmma::load_matrix_sync(bk[ni], &KS[(n0 + ni * 16) * QKLD + k0], QKLD);
                #pragma unroll
                for (int mi = 0; mi < 2; mi++)
                    #pragma unroll
                    for (int ni = 0; ni < 2; ni++)
                        wmma::mma_sync(sf[mi][ni], aq[mi], bk[ni], sf[mi][ni]);
            }
            #pragma unroll
            for (int mi = 0; mi < 2; mi++)
                #pragma unroll
                for (int ni = 0; ni < 2; ni++) {
                    #pragma unroll
                    for (int t = 0; t < sf[mi][ni].num_elements; t++)
                        sf[mi][ni].x[t] *= scale;
                    wmma::store_matrix_sync(&PS[(m0 + mi * 16) * PLD + n0 + ni * 16],
                                            sf[mi][ni], PLD, wmma::mem_row_major);
                }
        }
        __syncthreads();

        // --- softmax (no max shift: |s| <= 11.33): p = exp(s), mask, round ---
        {
            const int r    = tid >> 1;            // 0..127
            const int c0   = (tid & 1) * 32;
            const int rowg = qm0 + r;
            const bool edge = (kn0 + 63 > rowg);
            float rs = 0.0f;
            #pragma unroll
            for (int c = 0; c < 32; c++) {
                const int col = c0 + c;
                float s = PS[r * PLD + col];
                float p = (edge && (kn0 + col) > rowg) ? 0.0f : __expf(s);
                p = f2tf32f(p);
                PS[r * PLD + col] = p;
                rs += p;
            }
            rs += __shfl_xor_sync(0xffffffffu, rs, 1);
            if (!(tid & 1)) LS[r] += rs;
        }
        __syncthreads();

        // --- O += P V (single tf32), warp tile 32(m) x 64(n) ---
        {
            const int n0p = wn * 64;
            #pragma unroll
            for (int k0 = 0; k0 < 64; k0 += 8) {
                wmma::fragment<wmma::matrix_a, 16, 16, 8,
                               wmma::precision::tf32, wmma::row_major> ap[2];
                wmma::fragment<wmma::matrix_b, 16, 16, 8,
                               wmma::precision::tf32, wmma::row_major> bv[4];
                #pragma unroll
                for (int mi = 0; mi < 2; mi++)
                    wmma::load_matrix_sync(ap[mi], &PS[(m0 + mi * 16) * PLD + k0], PLD);
                #pragma unroll
                for (int ni = 0; ni < 4; ni++)
                    wmma::load_matrix_sync(bv[ni], &VS[k0 * QKLD + n0p + ni * 16], QKLD);
                #pragma unroll
                for (int mi = 0; mi < 2; mi++)
                    #pragma unroll
                    for (int ni = 0; ni < 4; ni++)
                        wmma::mma_sync(ofrag[mi][ni], ap[mi], bv[ni], ofrag[mi][ni]);
            }
        }
    }

    // --- epilogue: O -> smem (reuse QS), normalize by LS, write y [B,S,E] ---
    __syncthreads();
    {
        const int n0p = wn * 64;
        #pragma unroll
        for (int mi = 0; mi < 2; mi++)
            #pragma unroll
            for (int ni = 0; ni < 4; ni++)
                wmma::store_matrix_sync(&QS[(m0 + mi * 16) * QKLD + n0p + ni * 16],
                                        ofrag[mi][ni], QKLD, wmma::mem_row_major);
    }
    __syncthreads();
    for (int e = tid; e < 128 * 32; e += 256) {
        const int i  = e >> 5;
        const int d4 = (e & 31) << 2;
        const float invl = 1.0f / LS[i];
        float* yp = Yg + ((size_t)(b * SS + qm0 + i)) * EE + h * DD + d4;
        *(float4*)yp = make_float4(QS[i * QKLD + d4 + 0] * invl,
                                   QS[i * QKLD + d4 + 1] * invl,
                                   QS[i * QKLD + d4 + 2] * invl,
                                   QS[i * QKLD + d4 + 3] * invl);
    }
}

// ---------------------------------------------------------------------------
// Launch
// ---------------------------------------------------------------------------
extern "C" void kernel_launch(void* const* d_in, const int* in_sizes, int n_in,
                              void* d_out, int out_size)
{
    const float* x      = (const float*)d_in[0];
    const float* w_qkv  = (const float*)d_in[1];
    const float* w_proj = (const float*)d_in[2];
    float* out          = (float*)d_out;

    float *q_p, *k_p, *v_p, *y_p;
    cudaGetSymbolAddress((void**)&q_p, g_q);
    cudaGetSymbolAddress((void**)&k_p, g_k);
    cudaGetSymbolAddress((void**)&v_p, g_v);
    cudaGetSymbolAddress((void**)&y_p, g_y);

    cudaFuncSetAttribute(flash_attn_tc, cudaFuncAttributeMaxDynamicSharedMemorySize,
                         FL3_BYTES);

    // 1) QKV projection (tf32 wmma) with fused head-split
    gemm_tf32<1><<<dim3(QKVN / 128, MM / 128), 256>>>(x, w_qkv, q_p, k_p, v_p,
                                                      MM, QKVN, EE);

    // 2) RoPE + RMSNorm in-place on q,k
    rope_norm<<<dim3(HH, SS, BB), 64>>>(q_p, k_p);

    // 3) Tensor-core causal flash attention (v2)
    flash_attn_tc<<<dim3(SS / 128, BB * HH), 256, FL3_BYTES>>>(q_p, k_p, v_p, y_p);

    // 4) Output projection (tf32 wmma)
    gemm_tf32<0><<<dim3(EE / 128, MM / 128), 256>>>(y_p, w_proj, out, nullptr, nullptr,
                                                    MM, EE, EE);
}